// round 10
// baseline (speedup 1.0000x reference)
#include <cuda_runtime.h>
#include <cuda_bf16.h>
#include <math.h>
#include <stdint.h>

#define BB 256
#define DD 512
#define PP 5
#define NC 11003
#define SEGC 6
#define SCALE_ 28.0f
#define ALPHA_ 0.6f
#define BETA_ 0.4f
#define SP_ 10.0f
#define SN_ 40.0f

#define NCHUNK 172         // ceil(11008/64)
#define NPIX (1280*4096)

// ---------------- device scratch ----------------
__device__ float g_XN[2*BB*DD];
__device__ float g_tnT[DD*BB];
__device__ float g_penN[PP*BB*DD];
__device__ float g_aeT[PP*DD*BB];
__device__ __align__(16) __nv_bfloat16 g_Ahi[2*BB*DD];
__device__ __align__(16) __nv_bfloat16 g_Alo[2*BB*DD];
__device__ float g_chunkMax[NCHUNK*2*BB];
__device__ float g_chunkSum[NCHUNK*2*BB];
__device__ float g_labLogit[2*BB];
__device__ float g_rowLoss[2*BB];
__device__ float g_sims[PP*BB*BB];
__device__ int   g_boost1[PP*BB];
__device__ int   g_boost2[PP*BB];
__device__ int   g_vmInt, g_tmInt;
__device__ double g_accMask, g_accGlob, g_accLocal;
__device__ int g_work[4];
__device__ int g_arr[4], g_dep[4];

// ---------------- fast transcendentals (FMA-only) ----------------
__device__ __forceinline__ float fexp(float x) {
    x = fmaxf(fminf(x, 88.0f), -87.0f);
    float t = x * 1.4426950408889634f;
    float z = t + 12582912.0f;
    int i = __float_as_int(z) - 0x4B400000;
    float f = t - (z - 12582912.0f);
    float p = 1.5252733804059841e-05f;
    p = fmaf(p, f, 1.5403530393381610e-04f);
    p = fmaf(p, f, 1.3333558146428443e-03f);
    p = fmaf(p, f, 9.6181291076284772e-03f);
    p = fmaf(p, f, 5.5504108664821580e-02f);
    p = fmaf(p, f, 2.4022650695910071e-01f);
    p = fmaf(p, f, 6.9314718055994531e-01f);
    p = fmaf(p, f, 1.0f);
    return __int_as_float((i + 127) << 23) * p;
}
__device__ __forceinline__ float flog(float x) {
    int ix = __float_as_int(x);
    int e = (ix - 0x3f3504f3) >> 23;
    float m = __int_as_float(ix - (e << 23));
    float u = m - 1.0f;
    float z = u * u;
    float p = 7.0376836292e-2f;
    p = fmaf(p, u, -1.1514610310e-1f);
    p = fmaf(p, u,  1.1676998740e-1f);
    p = fmaf(p, u, -1.2420140846e-1f);
    p = fmaf(p, u,  1.4249322787e-1f);
    p = fmaf(p, u, -1.6668057665e-1f);
    p = fmaf(p, u,  2.0000714765e-1f);
    p = fmaf(p, u, -2.4999993993e-1f);
    p = fmaf(p, u,  3.3333331174e-1f);
    float y = p * u * z - 0.5f * z;
    return fmaf((float)e, 0.69314718055994531f, u + y);
}
__device__ __forceinline__ float softplus_f(float x) {
    if (x > 20.f) return x;
    return flog(1.0f + fexp(x));
}
__device__ __forceinline__ float warpReduceF(float v) {
    #pragma unroll
    for (int off = 16; off > 0; off >>= 1) v += __shfl_xor_sync(0xffffffffu, v, off);
    return v;
}
__device__ __forceinline__ void blockAtomicAddF(float v, double* target, float* swarp) {
    int w = threadIdx.x >> 5, lane = threadIdx.x & 31;
    v = warpReduceF(v);
    if (lane == 0) swarp[w] = v;
    __syncthreads();
    if (threadIdx.x == 0) {
        float s = 0.f;
        for (int i = 0; i < 8; i++) s += swarp[i];
        atomicAdd(target, (double)s);
    }
    __syncthreads();
}
__device__ __forceinline__ bool readMask(const uint8_t* m, int idx, int isInt) {
    return isInt ? (((const int*)m)[idx] != 0) : (m[idx] != 0);
}
__device__ __forceinline__ float rsqrt_nt(float s) {
    float inv = rsqrtf(s);
    return inv * (1.5f - 0.5f * s * inv * inv);
}
__device__ __forceinline__ void mma_bf16(float* c, const uint32_t* a, const uint32_t* b) {
    asm volatile(
        "mma.sync.aligned.m16n8k16.row.col.f32.bf16.bf16.f32 "
        "{%0,%1,%2,%3}, {%4,%5,%6,%7}, {%8,%9}, {%0,%1,%2,%3};"
        : "+f"(c[0]), "+f"(c[1]), "+f"(c[2]), "+f"(c[3])
        : "r"(a[0]), "r"(a[1]), "r"(a[2]), "r"(a[3]), "r"(b[0]), "r"(b[1]));
}
__device__ __forceinline__ void ldsm_x4(uint32_t& r0, uint32_t& r1, uint32_t& r2, uint32_t& r3, uint32_t addr) {
    asm volatile("ldmatrix.sync.aligned.m8n8.x4.shared.b16 {%0,%1,%2,%3}, [%4];"
                 : "=r"(r0), "=r"(r1), "=r"(r2), "=r"(r3) : "r"(addr));
}
__device__ __forceinline__ void ldsm_x4t(uint32_t& r0, uint32_t& r1, uint32_t& r2, uint32_t& r3, uint32_t addr) {
    asm volatile("ldmatrix.sync.aligned.m8n8.x4.trans.shared.b16 {%0,%1,%2,%3}, [%4];"
                 : "=r"(r0), "=r"(r1), "=r"(r2), "=r"(r3) : "r"(addr));
}

// ---------------- grid barrier (arrive/depart, replay-safe) ----------------
__device__ __forceinline__ void gridBarrier(int ph, int nb) {
    __syncthreads();
    if (threadIdx.x == 0) {
        __threadfence();
        atomicAdd(&g_arr[ph], 1);
        while (*(volatile int*)&g_arr[ph] < nb) __nanosleep(64);
        __threadfence();
        atomicAdd(&g_dep[ph], 1);
    }
    __syncthreads();
}

// ================= phase bodies =================

__device__ void do_mask(int mblk, const float* __restrict__ seg, const int* __restrict__ masks) {
    __shared__ float swarp[8];
    int tid = mblk * 256 + threadIdx.x;
    long long pix0 = (long long)tid * 4;
    int n = (int)(pix0 >> 12);
    int hw = (int)(pix0 & 4095);
    const float* base = seg + (size_t)n * SEGC * 4096 + hw;

    float xx[SEGC][4];
    #pragma unroll
    for (int c = 0; c < SEGC; c++) {
        float4 v = *(const float4*)(base + (size_t)c * 4096);
        xx[c][0] = v.x; xx[c][1] = v.y; xx[c][2] = v.z; xx[c][3] = v.w;
    }
    int4 cl4 = *(const int4*)(masks + pix0);
    int cls[4] = {cl4.x, cl4.y, cl4.z, cl4.w};

    float acc = 0.f;
    #pragma unroll
    for (int j = 0; j < 4; j++) {
        float m = xx[0][j];
        #pragma unroll
        for (int c = 1; c < SEGC; c++) m = fmaxf(m, xx[c][j]);
        float s = 0.f, sel = 0.f;
        #pragma unroll
        for (int c = 0; c < SEGC; c++) {
            s += fexp(xx[c][j] - m);
            sel += (c == cls[j]) ? xx[c][j] : 0.f;
        }
        acc += m + flog(s) - sel;
    }
    blockAtomicAddF(acc, &g_accMask, swarp);
}

__device__ void do_normalize(char* smraw, int b, const float* __restrict__ v, const float* __restrict__ t,
                             const float* __restrict__ pe, const float* __restrict__ ae) {
    float* sred = (float*)smraw;
    const float* src;
    float* dst = nullptr;
    float* dstT = nullptr;
    int tcol = 0;
    bool isXN = false;
    if (b < 256) { src = v + (size_t)b*DD; dst = g_XN + (size_t)b*DD; isXN = true; }
    else if (b < 512) { int r = b - 256; src = t + (size_t)r*DD; dst = g_XN + (size_t)b*DD; dstT = g_tnT; tcol = r; isXN = true; }
    else if (b < 512 + PP*BB) { int k = b - 512; src = pe + (size_t)k*DD; dst = g_penN + (size_t)k*DD; }
    else { int k = b - 512 - PP*BB; int p = k / BB; int rr = k % BB;
           src = ae + (size_t)k*DD; dstT = g_aeT + (size_t)p*DD*BB; tcol = rr; }

    float s = 0.f;
    for (int d = threadIdx.x; d < DD; d += 256) { float x = src[d]; s += x*x; }
    sred[threadIdx.x] = s; __syncthreads();
    for (int st = 128; st > 0; st >>= 1) { if (threadIdx.x < st) sred[threadIdx.x] += sred[threadIdx.x + st]; __syncthreads(); }
    float inv = rsqrt_nt(sred[0]);
    __syncthreads();

    for (int d = threadIdx.x; d < DD; d += 256) {
        float x = src[d] * inv;
        if (dst)  dst[d] = x;
        if (dstT) dstT[d*BB + tcol] = x;
        if (isXN) {
            __nv_bfloat16 hi = __float2bfloat16(x);
            g_Ahi[(size_t)b*DD + d] = hi;
            g_Alo[(size_t)b*DD + d] = __float2bfloat16(x - __bfloat162float(hi));
        }
    }
}

__device__ void do_detect(const uint8_t* __restrict__ vm, const uint8_t* __restrict__ tm) {
    __shared__ int s0, s1;
    if (threadIdx.x == 0) { s0 = 0; s1 = 0; }
    __syncthreads();
    int a0 = 0, a1 = 0;
    for (int i = threadIdx.x; i < PP*BB; i += 256) {
        if (i & 3) { a0 |= vm[i]; a1 |= tm[i]; }
    }
    atomicOr(&s0, a0); atomicOr(&s1, a1);
    __syncthreads();
    if (threadIdx.x == 0) { g_vmInt = (s0 == 0) ? 1 : 0; g_tmInt = (s1 == 0) ? 1 : 0; }
}

// ---- GEMM tile (128 rows x 64 cols, K=512), W converted in-tile ----
// A smem: [m][k] rows of 72 bf16 (non-trans ldmatrix)
// B smem: [k][n] rows of 72 bf16 (trans ldmatrix), written from fp32 W
#define SA_STRIDE 72
#define OFF_AH 0
#define OFF_AL 18432
#define OFF_BH 36864
#define OFF_BL 46080
#define GEMM_SMEM 55296

__device__ void do_gemm(char* smraw, int chunk, int rt,
                        const float* __restrict__ W, const int* __restrict__ labels) {
    __nv_bfloat16* sAh = (__nv_bfloat16*)(smraw + OFF_AH);
    __nv_bfloat16* sAl = (__nv_bfloat16*)(smraw + OFF_AL);
    __nv_bfloat16* sBh = (__nv_bfloat16*)(smraw + OFF_BH);
    __nv_bfloat16* sBl = (__nv_bfloat16*)(smraw + OFF_BL);
    __shared__ float sAcc[8][64];
    __shared__ float sInv[64];

    const int rowBase = rt * 128;
    const int colBase = chunk * 64;
    const int t = threadIdx.x;
    const int w = t >> 5, lane = t & 31;
    const int lr = lane & 7, mi = lane >> 3;
    const uint32_t sbase = (uint32_t)__cvta_generic_to_shared(smraw);

    // A fragment offsets (non-trans, [m][k])
    const uint32_t aoff = (uint32_t)((w*16 + lr + (mi & 1)*8) * SA_STRIDE + (mi >> 1)*8) * 2;
    // B fragment offsets (trans, [k][n]): mat order (k0,n0),(k8,n0),(k0,n8),(k8,n8)
    uint32_t boff[4];
    #pragma unroll
    for (int q = 0; q < 4; q++)
        boff[q] = (uint32_t)(((mi & 1)*8 + lr) * SA_STRIDE + q*16 + (mi >> 1)*8) * 2;

    float acc[8][4];
    #pragma unroll
    for (int nf = 0; nf < 8; nf++)
        #pragma unroll
        for (int q = 0; q < 4; q++) acc[nf][q] = 0.f;

    const __nv_bfloat16* Ahi = g_Ahi + (size_t)rowBase*DD;
    const __nv_bfloat16* Alo = g_Alo + (size_t)rowBase*DD;

    // W conversion assignment: thread covers c-pair (2*(t&31), +1), d rows (t>>5) + 8*it
    const int cp = 2 * (t & 31);
    const int dbase = t >> 5;
    const int colg0 = colBase + cp, colg1 = colg0 + 1;
    const bool ok0 = colg0 < NC, ok1 = colg1 < NC;
    float ss0 = 0.f, ss1 = 0.f;

    for (int kc = 0; kc < 8; kc++) {
        int k0g = kc * 64;
        // A tiles (bf16, uint4 from L2-resident globals)
        #pragma unroll
        for (int it = 0; it < 4; it++) {
            int idx = t + it*256, row = idx >> 3, j = idx & 7;
            ((uint4*)sAh)[row*9 + j] = ((const uint4*)(Ahi + (size_t)row*DD + k0g))[j];
            ((uint4*)sAl)[row*9 + j] = ((const uint4*)(Alo + (size_t)row*DD + k0g))[j];
        }
        // B: fp32 W -> bf16 hi/lo into [k][n] smem + column sumsq
        #pragma unroll
        for (int it = 0; it < 8; it++) {
            int d = dbase + it*8;
            const float* wrow = W + (size_t)(k0g + d)*NC;
            float v0 = ok0 ? wrow[colg0] : 0.f;
            float v1 = ok1 ? wrow[colg1] : 0.f;
            ss0 = fmaf(v0, v0, ss0);
            ss1 = fmaf(v1, v1, ss1);
            __nv_bfloat16 h0 = __float2bfloat16(v0);
            __nv_bfloat16 h1 = __float2bfloat16(v1);
            __nv_bfloat16 l0 = __float2bfloat16(v0 - __bfloat162float(h0));
            __nv_bfloat16 l1 = __float2bfloat16(v1 - __bfloat162float(h1));
            __nv_bfloat162 hp; hp.x = h0; hp.y = h1;
            __nv_bfloat162 lp; lp.x = l0; lp.y = l1;
            *(__nv_bfloat162*)&sBh[d*SA_STRIDE + cp] = hp;
            *(__nv_bfloat162*)&sBl[d*SA_STRIDE + cp] = lp;
        }
        __syncthreads();

        #pragma unroll
        for (int ks = 0; ks < 4; ks++) {
            uint32_t kaddA = ks * 32;          // 16 k * 2B within A row
            uint32_t kaddB = ks * 2304;        // 16 k rows * 144B in B
            uint32_t ah[4], al[4];
            ldsm_x4(ah[0], ah[1], ah[2], ah[3], sbase + OFF_AH + aoff + kaddA);
            ldsm_x4(al[0], al[1], al[2], al[3], sbase + OFF_AL + aoff + kaddA);
            #pragma unroll
            for (int q = 0; q < 4; q++) {
                uint32_t bh[4], bl[4];
                ldsm_x4t(bh[0], bh[1], bh[2], bh[3], sbase + OFF_BH + boff[q] + kaddB);
                ldsm_x4t(bl[0], bl[1], bl[2], bl[3], sbase + OFF_BL + boff[q] + kaddB);
                mma_bf16(acc[2*q],   ah, bh);
                mma_bf16(acc[2*q],   al, bh);
                mma_bf16(acc[2*q],   ah, bl);
                mma_bf16(acc[2*q+1], ah, bh+2);
                mma_bf16(acc[2*q+1], al, bh+2);
                mma_bf16(acc[2*q+1], ah, bl+2);
            }
        }
        __syncthreads();
    }

    // reduce per-column sumsq: 8 partials per column
    sAcc[dbase][cp] = ss0;
    sAcc[dbase][cp + 1] = ss1;
    __syncthreads();
    if (t < 64) {
        float s = 0.f;
        #pragma unroll
        for (int i = 0; i < 8; i++) s += sAcc[i][t];
        sInv[t] = rsqrt_nt(s);
    }
    __syncthreads();

    const int g = lane >> 2, tig = lane & 3;
    #pragma unroll
    for (int h = 0; h < 2; h++) {
        int gr = rowBase + w*16 + g + h*8;
        int lab = labels[gr & 255];
        float lg[8][2];
        float m = -INFINITY;
        #pragma unroll
        for (int nf = 0; nf < 8; nf++) {
            #pragma unroll
            for (int j = 0; j < 2; j++) {
                int lc = nf*8 + tig*2 + j;
                int col = colBase + lc;
                float x;
                if (col < NC) {
                    x = SCALE_ * acc[nf][h*2 + j] * sInv[lc];
                    if (col == lab) g_labLogit[gr] = x;
                } else {
                    x = -INFINITY;
                }
                lg[nf][j] = x;
                m = fmaxf(m, x);
            }
        }
        m = fmaxf(m, __shfl_xor_sync(0xffffffffu, m, 1));
        m = fmaxf(m, __shfl_xor_sync(0xffffffffu, m, 2));
        float s = 0.f;
        #pragma unroll
        for (int nf = 0; nf < 8; nf++)
            #pragma unroll
            for (int j = 0; j < 2; j++) s += fexp(lg[nf][j] - m);
        s += __shfl_xor_sync(0xffffffffu, s, 1);
        s += __shfl_xor_sync(0xffffffffu, s, 2);
        if (tig == 0) {
            g_chunkMax[chunk*512 + gr] = m;
            g_chunkSum[chunk*512 + gr] = s;
        }
    }
}

__device__ void do_sims(char* smraw, int rg, int p) {
    float* sP = (float*)smraw;
    int j = threadIdx.x;
    for (int idx = j; idx < 16*DD; idx += 256) {
        int rr = idx / DD, d = idx % DD;
        sP[d*17 + rr] = g_penN[((size_t)p*BB + rg*16 + rr)*DD + d];
    }
    __syncthreads();

    float acc[16];
    #pragma unroll
    for (int rr = 0; rr < 16; rr++) acc[rr] = 0.f;
    const float* aT = g_aeT + (size_t)p*DD*BB;
    for (int d = 0; d < DD; d++) {
        float b = aT[d*BB + j];
        #pragma unroll
        for (int rr = 0; rr < 16; rr++) acc[rr] += sP[d*17 + rr] * b;
    }
    float* S = g_sims + (size_t)p*BB*BB;
    #pragma unroll
    for (int rr = 0; rr < 16; rr++) S[(size_t)(rg*16 + rr)*BB + j] = acc[rr];
    __syncthreads();
}

__device__ void do_global(char* smraw, int rg, const int* __restrict__ labels) {
    float* sV = (float*)smraw;
    __shared__ float swarp[8];
    int j = threadIdx.x;
    for (int idx = j; idx < 16*DD; idx += 256) {
        int rr = idx / DD, d = idx % DD;
        sV[d*17 + rr] = g_XN[(size_t)(rg*16 + rr)*DD + d];
    }
    __syncthreads();

    float acc[16];
    #pragma unroll
    for (int rr = 0; rr < 16; rr++) acc[rr] = 0.f;
    for (int d = 0; d < DD; d++) {
        float b = g_tnT[d*BB + j];
        #pragma unroll
        for (int rr = 0; rr < 16; rr++) acc[rr] += sV[d*17 + rr] * b;
    }

    int labj = labels[j];
    float lsum = 0.f;
    #pragma unroll
    for (int rr = 0; rr < 16; rr++) {
        bool match = (labels[rg*16 + rr] == labj);
        float s = acc[rr];
        lsum += match ? softplus_f(-SP_ * (s - ALPHA_)) : softplus_f(SN_ * (s - BETA_));
    }
    blockAtomicAddF(lsum, &g_accGlob, swarp);
}

__device__ void do_boost(char* smraw, int p) {
    float* srow = (float*)smraw;
    float* scol = (float*)(smraw + 1024);
    int c = threadIdx.x;
    const float* S = g_sims + (size_t)p*BB*BB;
    srow[c] = S[(size_t)p*BB + c];
    scol[c] = S[(size_t)c*BB + p];
    __syncthreads();

    float vr = srow[c];
    int cnt = 0;
    for (int k = 0; k < BB; k++) { float o = srow[k]; cnt += (o > vr) || (o == vr && k < c); }
    bool inRow = cnt < 8;
    cnt = 0;
    for (int r = 0; r < BB; r++) { float o = S[(size_t)r*BB + c]; cnt += (o > vr) || (o == vr && r < p); }
    bool inCol = cnt < 8;
    g_boost1[p*BB + c] = (inRow && inCol) ? 1 : 0;

    float vc = scol[c];
    cnt = 0;
    for (int k = 0; k < BB; k++) { float o = scol[k]; cnt += (o > vc) || (o == vc && k < c); }
    bool inColP = cnt < 8;
    cnt = 0;
    for (int cc = 0; cc < BB; cc++) { float o = S[(size_t)c*BB + cc]; cnt += (o > vc) || (o == vc && cc < p); }
    bool inRowR = cnt < 8;
    g_boost2[p*BB + c] = (inColP && inRowR) ? 1 : 0;
    __syncthreads();
}

__device__ void do_reduce(int task) {
    int w = threadIdx.x >> 5, lane = threadIdx.x & 31;
    int row = task * 8 + w;
    float m = -INFINITY;
    for (int j = lane; j < NCHUNK; j += 32) m = fmaxf(m, g_chunkMax[j*512 + row]);
    #pragma unroll
    for (int off = 16; off > 0; off >>= 1) m = fmaxf(m, __shfl_xor_sync(0xffffffffu, m, off));
    float s = 0.f;
    for (int j = lane; j < NCHUNK; j += 32) s += g_chunkSum[j*512 + row] * fexp(g_chunkMax[j*512 + row] - m);
    s = warpReduceF(s);
    if (lane == 0) g_rowLoss[row] = m + flog(s) - g_labLogit[row];
}

__device__ void do_local(int task, const int* __restrict__ labels,
                         const uint8_t* __restrict__ vmask, const uint8_t* __restrict__ tmask) {
    __shared__ float swarp[8];
    int r = task & 255;
    int p = task >> 8;
    int c = threadIdx.x;

    int vmInt = g_vmInt, tmInt = g_tmInt;
    float s = g_sims[((size_t)p*BB + r)*BB + c];
    bool match = (labels[r] == labels[c]);
    float Lp = softplus_f(-SP_ * (s - ALPHA_));
    float Ln = softplus_f(SN_ * (s - BETA_));

    bool pmr = readMask(vmask, r*PP + p, vmInt);
    bool pmc = readMask(vmask, c*PP + p, vmInt);
    bool amc = readMask(tmask, c*PP + p, tmInt);

    float val = 0.f;
    if (pmr && amc) val += (match || g_boost1[p*BB + c]) ? Lp : Ln;
    if (pmr && pmc && amc) val += (match || g_boost2[p*BB + r]) ? Lp : Ln;

    blockAtomicAddF(val, &g_accLocal, swarp);
}

__device__ void do_finalize(char* smraw, float* __restrict__ out) {
    double* sred = (double*)smraw;
    int t = threadIdx.x;
    sred[t] = (double)g_rowLoss[t] + (double)g_rowLoss[t + 256];
    __syncthreads();
    for (int s = 128; s > 0; s >>= 1) {
        if (t < s) sred[t] += sred[t + s];
        __syncthreads();
    }
    if (t == 0) {
        out[0] = (float)(sred[0] / 256.0);
        out[1] = (float)(5.0 * g_accMask / ((double)NPIX));
        out[2] = (float)(2.0 * g_accGlob / 256.0);
        out[3] = (float)(g_accLocal / (256.0 * 5.0));
    }
    __syncthreads();
}

// ================= mega kernel =================
__global__ __launch_bounds__(256, 2) void mega_kernel(
    const float* __restrict__ visual, const float* __restrict__ textual,
    const float* __restrict__ part, const float* __restrict__ attribute,
    const float* __restrict__ seg, const float* __restrict__ W,
    const int* __restrict__ labels, const int* __restrict__ masks,
    const uint8_t* __restrict__ vmask, const uint8_t* __restrict__ tmask,
    float* __restrict__ out)
{
    extern __shared__ __align__(16) char sm[];
    __shared__ int s_task;
    const int NBLK = gridDim.x;

    // ---- Phase 0: normalize + detect only (tiny) ----
    {
        const int T_NORM = 512 + 2*PP*BB;            // 3072
        const int TOT = T_NORM + 1;
        for (;;) {
            __syncthreads();
            if (threadIdx.x == 0) s_task = atomicAdd(&g_work[0], 1);
            __syncthreads();
            int task = s_task;
            if (task >= TOT) break;
            if (task < T_NORM) do_normalize(sm, task, visual, textual, part, attribute);
            else do_detect(vmask, tmask);
        }
    }
    gridBarrier(0, NBLK);

    // ---- Phase 1: GEMM tiles (first) + mask + sims + global ----
    {
        const int T_GEMM = NCHUNK * 4;               // 688
        const int T_MASK = NPIX / 1024;              // 5120
        const int TOT = T_GEMM + T_MASK + 80 + 16;
        for (;;) {
            __syncthreads();
            if (threadIdx.x == 0) s_task = atomicAdd(&g_work[1], 1);
            __syncthreads();
            int task = s_task;
            if (task >= TOT) break;
            if (task < T_GEMM) do_gemm(sm, task % NCHUNK, task / NCHUNK, W, labels);
            else if (task < T_GEMM + T_MASK) do_mask(task - T_GEMM, seg, masks);
            else if (task < T_GEMM + T_MASK + 80) { int u = task - T_GEMM - T_MASK; do_sims(sm, u & 15, u >> 4); }
            else do_global(sm, task - T_GEMM - T_MASK - 80, labels);
        }
    }
    gridBarrier(1, NBLK);

    // ---- Phase 2: boost + instance reduce ----
    {
        const int TOT = 5 + 64;
        for (;;) {
            __syncthreads();
            if (threadIdx.x == 0) s_task = atomicAdd(&g_work[2], 1);
            __syncthreads();
            int task = s_task;
            if (task >= TOT) break;
            if (task < 5) do_boost(sm, task);
            else do_reduce(task - 5);
        }
    }
    gridBarrier(2, NBLK);

    // ---- Phase 3: local align ----
    {
        const int TOT = BB * PP;                     // 1280
        for (;;) {
            __syncthreads();
            if (threadIdx.x == 0) s_task = atomicAdd(&g_work[3], 1);
            __syncthreads();
            int task = s_task;
            if (task >= TOT) break;
            do_local(task, labels, vmask, tmask);
        }
    }
    gridBarrier(3, NBLK);

    // ---- finalize + state reset (block 0 only) ----
    if (blockIdx.x == 0) {
        do_finalize(sm, out);
        if (threadIdx.x == 0) {
            for (int ph = 0; ph < 4; ph++)
                while (*(volatile int*)&g_dep[ph] < NBLK) __nanosleep(64);
            for (int ph = 0; ph < 4; ph++) { g_arr[ph] = 0; g_dep[ph] = 0; g_work[ph] = 0; }
            g_accMask = 0.0; g_accGlob = 0.0; g_accLocal = 0.0;
            __threadfence();
        }
    }
}

// ---------------- launch ----------------
extern "C" void kernel_launch(void* const* d_in, const int* in_sizes, int n_in,
                              void* d_out, int out_size) {
    const float* visual    = (const float*)d_in[0];
    const float* textual   = (const float*)d_in[1];
    const float* part      = (const float*)d_in[2];
    const float* attribute = (const float*)d_in[3];
    const float* seg       = (const float*)d_in[4];
    const float* W         = (const float*)d_in[5];
    const int*   labels    = (const int*)d_in[6];
    const int*   masks     = (const int*)d_in[7];
    const uint8_t* vmask   = (const uint8_t*)d_in[8];
    const uint8_t* tmask   = (const uint8_t*)d_in[9];
    float* out = (float*)d_out;

    static int grid = 0;
    if (!grid) {
        cudaFuncSetAttribute(mega_kernel, cudaFuncAttributeMaxDynamicSharedMemorySize, GEMM_SMEM);
        int nsm = 0, occ = 0;
        cudaDeviceGetAttribute(&nsm, cudaDevAttrMultiProcessorCount, 0);
        cudaOccupancyMaxActiveBlocksPerMultiprocessor(&occ, mega_kernel, 256, GEMM_SMEM);
        if (nsm <= 0) nsm = 148;
        if (occ < 1) occ = 1;
        if (occ > 2) occ = 2;
        grid = nsm * occ;
    }

    mega_kernel<<<grid, 256, GEMM_SMEM>>>(visual, textual, part, attribute, seg, W,
                                          labels, masks, vmask, tmask, out);
}

// round 11
// speedup vs baseline: 1.0689x; 1.0689x over previous
#include <cuda_runtime.h>
#include <cuda_bf16.h>
#include <math.h>
#include <stdint.h>

#define BB 256
#define DD 512
#define PP 5
#define NC 11003
#define NCPAD 11008
#define SEGC 6
#define SCALE_ 28.0f
#define ALPHA_ 0.6f
#define BETA_ 0.4f
#define SP_ 10.0f
#define SN_ 40.0f

#define NCHUNK 172         // ceil(11008/64)
#define NPIX (1280*4096)

// ---------------- device scratch ----------------
__device__ float g_XN[2*BB*DD];
__device__ float g_tnT[DD*BB];
__device__ float g_penN[PP*BB*DD];
__device__ float g_aeT[PP*DD*BB];
__device__ float g_sumsq[NCPAD];               // zeroed at end of each run (and at load)
__device__ __align__(16) __nv_bfloat16 g_Ahi[2*BB*DD];
__device__ __align__(16) __nv_bfloat16 g_Alo[2*BB*DD];
__device__ __align__(16) __nv_bfloat16 g_Bhi[NCPAD*DD];
__device__ __align__(16) __nv_bfloat16 g_Blo[NCPAD*DD];
__device__ float g_chunkMax[NCHUNK*2*BB];
__device__ float g_chunkSum[NCHUNK*2*BB];
__device__ float g_labLogit[2*BB];
__device__ float g_rowLoss[2*BB];
__device__ float g_sims[PP*BB*BB];
__device__ int   g_boost1[PP*BB];
__device__ int   g_boost2[PP*BB];
__device__ int   g_vmInt, g_tmInt;
__device__ double g_accMask, g_accGlob, g_accLocal;
__device__ int g_work[4];
__device__ int g_arr[4], g_dep[4];

// ---------------- fast transcendentals (FMA-only) ----------------
__device__ __forceinline__ float fexp(float x) {
    x = fmaxf(fminf(x, 88.0f), -87.0f);
    float t = x * 1.4426950408889634f;
    float z = t + 12582912.0f;
    int i = __float_as_int(z) - 0x4B400000;
    float f = t - (z - 12582912.0f);
    float p = 1.5252733804059841e-05f;
    p = fmaf(p, f, 1.5403530393381610e-04f);
    p = fmaf(p, f, 1.3333558146428443e-03f);
    p = fmaf(p, f, 9.6181291076284772e-03f);
    p = fmaf(p, f, 5.5504108664821580e-02f);
    p = fmaf(p, f, 2.4022650695910071e-01f);
    p = fmaf(p, f, 6.9314718055994531e-01f);
    p = fmaf(p, f, 1.0f);
    return __int_as_float((i + 127) << 23) * p;
}
__device__ __forceinline__ float flog(float x) {
    int ix = __float_as_int(x);
    int e = (ix - 0x3f3504f3) >> 23;
    float m = __int_as_float(ix - (e << 23));
    float u = m - 1.0f;
    float z = u * u;
    float p = 7.0376836292e-2f;
    p = fmaf(p, u, -1.1514610310e-1f);
    p = fmaf(p, u,  1.1676998740e-1f);
    p = fmaf(p, u, -1.2420140846e-1f);
    p = fmaf(p, u,  1.4249322787e-1f);
    p = fmaf(p, u, -1.6668057665e-1f);
    p = fmaf(p, u,  2.0000714765e-1f);
    p = fmaf(p, u, -2.4999993993e-1f);
    p = fmaf(p, u,  3.3333331174e-1f);
    float y = p * u * z - 0.5f * z;
    return fmaf((float)e, 0.69314718055994531f, u + y);
}
__device__ __forceinline__ float softplus_f(float x) {
    if (x > 20.f) return x;
    return flog(1.0f + fexp(x));
}
__device__ __forceinline__ float warpReduceF(float v) {
    #pragma unroll
    for (int off = 16; off > 0; off >>= 1) v += __shfl_xor_sync(0xffffffffu, v, off);
    return v;
}
__device__ __forceinline__ void blockAtomicAddF(float v, double* target, float* swarp) {
    int w = threadIdx.x >> 5, lane = threadIdx.x & 31;
    v = warpReduceF(v);
    if (lane == 0) swarp[w] = v;
    __syncthreads();
    if (threadIdx.x == 0) {
        float s = 0.f;
        for (int i = 0; i < 8; i++) s += swarp[i];
        atomicAdd(target, (double)s);
    }
    __syncthreads();
}
__device__ __forceinline__ bool readMask(const uint8_t* m, int idx, int isInt) {
    return isInt ? (((const int*)m)[idx] != 0) : (m[idx] != 0);
}
__device__ __forceinline__ float rsqrt_nt(float s) {
    float inv = rsqrtf(s);
    return inv * (1.5f - 0.5f * s * inv * inv);
}
__device__ __forceinline__ void mma_bf16(float* c, const uint32_t* a, const uint32_t* b) {
    asm volatile(
        "mma.sync.aligned.m16n8k16.row.col.f32.bf16.bf16.f32 "
        "{%0,%1,%2,%3}, {%4,%5,%6,%7}, {%8,%9}, {%0,%1,%2,%3};"
        : "+f"(c[0]), "+f"(c[1]), "+f"(c[2]), "+f"(c[3])
        : "r"(a[0]), "r"(a[1]), "r"(a[2]), "r"(a[3]), "r"(b[0]), "r"(b[1]));
}
__device__ __forceinline__ void ldsm_x4(uint32_t& r0, uint32_t& r1, uint32_t& r2, uint32_t& r3, uint32_t addr) {
    asm volatile("ldmatrix.sync.aligned.m8n8.x4.shared.b16 {%0,%1,%2,%3}, [%4];"
                 : "=r"(r0), "=r"(r1), "=r"(r2), "=r"(r3) : "r"(addr));
}

// ---------------- grid barrier (arrive/depart, replay-safe) ----------------
__device__ __forceinline__ void gridBarrier(int ph, int nb) {
    __syncthreads();
    if (threadIdx.x == 0) {
        __threadfence();
        atomicAdd(&g_arr[ph], 1);
        while (*(volatile int*)&g_arr[ph] < nb) __nanosleep(64);
        __threadfence();
        atomicAdd(&g_dep[ph], 1);
    }
    __syncthreads();
}

// ================= phase bodies =================

// mask loss: 8 pixels per thread
__device__ void do_mask(int mblk, const float* __restrict__ seg, const int* __restrict__ masks) {
    __shared__ float swarp[8];
    int tid = mblk * 256 + threadIdx.x;
    long long pix0 = (long long)tid * 8;
    int n = (int)(pix0 >> 12);
    int hw = (int)(pix0 & 4095);
    const float* base = seg + (size_t)n * SEGC * 4096 + hw;

    float xx[SEGC][8];
    #pragma unroll
    for (int c = 0; c < SEGC; c++) {
        float4 v0 = *(const float4*)(base + (size_t)c * 4096);
        float4 v1 = *(const float4*)(base + (size_t)c * 4096 + 4);
        xx[c][0] = v0.x; xx[c][1] = v0.y; xx[c][2] = v0.z; xx[c][3] = v0.w;
        xx[c][4] = v1.x; xx[c][5] = v1.y; xx[c][6] = v1.z; xx[c][7] = v1.w;
    }
    int4 ca = *(const int4*)(masks + pix0);
    int4 cb = *(const int4*)(masks + pix0 + 4);
    int cls[8] = {ca.x, ca.y, ca.z, ca.w, cb.x, cb.y, cb.z, cb.w};

    float acc = 0.f;
    #pragma unroll
    for (int j = 0; j < 8; j++) {
        float m = xx[0][j];
        #pragma unroll
        for (int c = 1; c < SEGC; c++) m = fmaxf(m, xx[c][j]);
        float s = 0.f, sel = 0.f;
        #pragma unroll
        for (int c = 0; c < SEGC; c++) {
            s += fexp(xx[c][j] - m);
            sel += (c == cls[j]) ? xx[c][j] : 0.f;
        }
        acc += m + flog(s) - sel;
    }
    blockAtomicAddF(acc, &g_accMask, swarp);
}

__device__ void do_cvtW(char* smraw, int task, const float* __restrict__ W) {
    float (*tile)[33] = (float(*)[33])smraw;
    int tx = threadIdx.x & 31, ty = threadIdx.x >> 5;
    int c0 = (task % 344) * 32, d0 = (task / 344) * 32;
    #pragma unroll
    for (int i = 0; i < 4; i++) {
        int d = d0 + ty + i*8, c = c0 + tx;
        tile[ty + i*8][tx] = (c < NC) ? W[(size_t)d*NC + c] : 0.f;
    }
    __syncthreads();
    #pragma unroll
    for (int i = 0; i < 4; i++) {
        int cl = ty + i*8;
        int c = c0 + cl, d = d0 + tx;
        float v = tile[tx][cl];
        __nv_bfloat16 hi = __float2bfloat16(v);
        g_Bhi[(size_t)c*DD + d] = hi;
        g_Blo[(size_t)c*DD + d] = __float2bfloat16(v - __bfloat162float(hi));
        float ss = warpReduceF(v * v);
        if (tx == 0) atomicAdd(&g_sumsq[c], ss);
    }
    __syncthreads();
}

__device__ void do_normalize(char* smraw, int b, const float* __restrict__ v, const float* __restrict__ t,
                             const float* __restrict__ pe, const float* __restrict__ ae) {
    float* sred = (float*)smraw;
    const float* src;
    float* dst = nullptr;
    float* dstT = nullptr;
    int tcol = 0;
    bool isXN = false;
    if (b < 256) { src = v + (size_t)b*DD; dst = g_XN + (size_t)b*DD; isXN = true; }
    else if (b < 512) { int r = b - 256; src = t + (size_t)r*DD; dst = g_XN + (size_t)b*DD; dstT = g_tnT; tcol = r; isXN = true; }
    else if (b < 512 + PP*BB) { int k = b - 512; src = pe + (size_t)k*DD; dst = g_penN + (size_t)k*DD; }
    else { int k = b - 512 - PP*BB; int p = k / BB; int rr = k % BB;
           src = ae + (size_t)k*DD; dstT = g_aeT + (size_t)p*DD*BB; tcol = rr; }

    float s = 0.f;
    for (int d = threadIdx.x; d < DD; d += 256) { float x = src[d]; s += x*x; }
    sred[threadIdx.x] = s; __syncthreads();
    for (int st = 128; st > 0; st >>= 1) { if (threadIdx.x < st) sred[threadIdx.x] += sred[threadIdx.x + st]; __syncthreads(); }
    float inv = rsqrt_nt(sred[0]);
    __syncthreads();

    for (int d = threadIdx.x; d < DD; d += 256) {
        float x = src[d] * inv;
        if (dst)  dst[d] = x;
        if (dstT) dstT[d*BB + tcol] = x;
        if (isXN) {
            __nv_bfloat16 hi = __float2bfloat16(x);
            g_Ahi[(size_t)b*DD + d] = hi;
            g_Alo[(size_t)b*DD + d] = __float2bfloat16(x - __bfloat162float(hi));
        }
    }
}

__device__ void do_detect(const uint8_t* __restrict__ vm, const uint8_t* __restrict__ tm) {
    __shared__ int s0, s1;
    if (threadIdx.x == 0) { s0 = 0; s1 = 0; }
    __syncthreads();
    int a0 = 0, a1 = 0;
    for (int i = threadIdx.x; i < PP*BB; i += 256) {
        if (i & 3) { a0 |= vm[i]; a1 |= tm[i]; }
    }
    atomicOr(&s0, a0); atomicOr(&s1, a1);
    __syncthreads();
    if (threadIdx.x == 0) { g_vmInt = (s0 == 0) ? 1 : 0; g_tmInt = (s1 == 0) ? 1 : 0; }
}

// ---- GEMM tile (128 rows x 64 cols, K=512) — R8 body, unchanged ----
#define SA_STRIDE 72
#define OFF_AH 0
#define OFF_AL 18432
#define OFF_BH 36864
#define OFF_BL 46080
#define GEMM_SMEM 55296

__device__ void do_gemm(char* smraw, int chunk, int rt, const int* __restrict__ labels) {
    __nv_bfloat16* sAh = (__nv_bfloat16*)(smraw + OFF_AH);
    __nv_bfloat16* sAl = (__nv_bfloat16*)(smraw + OFF_AL);
    __nv_bfloat16* sBh = (__nv_bfloat16*)(smraw + OFF_BH);
    __nv_bfloat16* sBl = (__nv_bfloat16*)(smraw + OFF_BL);
    __shared__ float sInv[64];

    const int rowBase = rt * 128;
    const int colBase = chunk * 64;
    const int t = threadIdx.x;
    const int w = t >> 5, lane = t & 31;
    const int lr = lane & 7, mi = lane >> 3;
    const uint32_t sbase = (uint32_t)__cvta_generic_to_shared(smraw);

    const uint32_t aoff = (uint32_t)((w*16 + lr + (mi & 1)*8) * SA_STRIDE + (mi >> 1)*8) * 2;
    uint32_t boff[4];
    #pragma unroll
    for (int q = 0; q < 4; q++)
        boff[q] = (uint32_t)((q*16 + (mi >> 1)*8 + lr) * SA_STRIDE + (mi & 1)*8) * 2;

    float acc[8][4];
    #pragma unroll
    for (int nf = 0; nf < 8; nf++)
        #pragma unroll
        for (int q = 0; q < 4; q++) acc[nf][q] = 0.f;

    const __nv_bfloat16* Ahi = g_Ahi + (size_t)rowBase*DD;
    const __nv_bfloat16* Alo = g_Alo + (size_t)rowBase*DD;
    const __nv_bfloat16* Bhi = g_Bhi + (size_t)colBase*DD;
    const __nv_bfloat16* Blo = g_Blo + (size_t)colBase*DD;

    if (t < 64) sInv[t] = rsqrt_nt(g_sumsq[colBase + t]);

    for (int kc = 0; kc < 8; kc++) {
        int k0g = kc * 64;
        #pragma unroll
        for (int it = 0; it < 4; it++) {
            int idx = t + it*256, row = idx >> 3, j = idx & 7;
            ((uint4*)sAh)[row*9 + j] = ((const uint4*)(Ahi + (size_t)row*DD + k0g))[j];
            ((uint4*)sAl)[row*9 + j] = ((const uint4*)(Alo + (size_t)row*DD + k0g))[j];
        }
        #pragma unroll
        for (int it = 0; it < 2; it++) {
            int idx = t + it*256, row = idx >> 3, j = idx & 7;
            ((uint4*)sBh)[row*9 + j] = ((const uint4*)(Bhi + (size_t)row*DD + k0g))[j];
            ((uint4*)sBl)[row*9 + j] = ((const uint4*)(Blo + (size_t)row*DD + k0g))[j];
        }
        __syncthreads();

        #pragma unroll
        for (int ks = 0; ks < 4; ks++) {
            uint32_t kadd = ks * 32;
            uint32_t ah[4], al[4];
            ldsm_x4(ah[0], ah[1], ah[2], ah[3], sbase + OFF_AH + aoff + kadd);
            ldsm_x4(al[0], al[1], al[2], al[3], sbase + OFF_AL + aoff + kadd);
            #pragma unroll
            for (int q = 0; q < 4; q++) {
                uint32_t bh[4], bl[4];
                ldsm_x4(bh[0], bh[1], bh[2], bh[3], sbase + OFF_BH + boff[q] + kadd);
                ldsm_x4(bl[0], bl[1], bl[2], bl[3], sbase + OFF_BL + boff[q] + kadd);
                mma_bf16(acc[2*q],   ah, bh);
                mma_bf16(acc[2*q],   al, bh);
                mma_bf16(acc[2*q],   ah, bl);
                mma_bf16(acc[2*q+1], ah, bh+2);
                mma_bf16(acc[2*q+1], al, bh+2);
                mma_bf16(acc[2*q+1], ah, bl+2);
            }
        }
        __syncthreads();
    }

    const int g = lane >> 2, tig = lane & 3;
    #pragma unroll
    for (int h = 0; h < 2; h++) {
        int gr = rowBase + w*16 + g + h*8;
        int lab = labels[gr & 255];
        float lg[8][2];
        float m = -INFINITY;
        #pragma unroll
        for (int nf = 0; nf < 8; nf++) {
            #pragma unroll
            for (int j = 0; j < 2; j++) {
                int lc = nf*8 + tig*2 + j;
                int col = colBase + lc;
                float x;
                if (col < NC) {
                    x = SCALE_ * acc[nf][h*2 + j] * sInv[lc];
                    if (col == lab) g_labLogit[gr] = x;
                } else {
                    x = -INFINITY;
                }
                lg[nf][j] = x;
                m = fmaxf(m, x);
            }
        }
        m = fmaxf(m, __shfl_xor_sync(0xffffffffu, m, 1));
        m = fmaxf(m, __shfl_xor_sync(0xffffffffu, m, 2));
        float s = 0.f;
        #pragma unroll
        for (int nf = 0; nf < 8; nf++)
            #pragma unroll
            for (int j = 0; j < 2; j++) s += fexp(lg[nf][j] - m);
        s += __shfl_xor_sync(0xffffffffu, s, 1);
        s += __shfl_xor_sync(0xffffffffu, s, 2);
        if (tig == 0) {
            g_chunkMax[chunk*512 + gr] = m;
            g_chunkSum[chunk*512 + gr] = s;
        }
    }
}

__device__ void do_sims(char* smraw, int rg, int p) {
    float* sP = (float*)smraw;
    int j = threadIdx.x;
    for (int idx = j; idx < 16*DD; idx += 256) {
        int rr = idx / DD, d = idx % DD;
        sP[d*17 + rr] = g_penN[((size_t)p*BB + rg*16 + rr)*DD + d];
    }
    __syncthreads();

    float acc[16];
    #pragma unroll
    for (int rr = 0; rr < 16; rr++) acc[rr] = 0.f;
    const float* aT = g_aeT + (size_t)p*DD*BB;
    for (int d = 0; d < DD; d++) {
        float b = aT[d*BB + j];
        #pragma unroll
        for (int rr = 0; rr < 16; rr++) acc[rr] += sP[d*17 + rr] * b;
    }
    float* S = g_sims + (size_t)p*BB*BB;
    #pragma unroll
    for (int rr = 0; rr < 16; rr++) S[(size_t)(rg*16 + rr)*BB + j] = acc[rr];
    __syncthreads();
}

__device__ void do_global(char* smraw, int rg, const int* __restrict__ labels) {
    float* sV = (float*)smraw;
    __shared__ float swarp[8];
    int j = threadIdx.x;
    for (int idx = j; idx < 16*DD; idx += 256) {
        int rr = idx / DD, d = idx % DD;
        sV[d*17 + rr] = g_XN[(size_t)(rg*16 + rr)*DD + d];
    }
    __syncthreads();

    float acc[16];
    #pragma unroll
    for (int rr = 0; rr < 16; rr++) acc[rr] = 0.f;
    for (int d = 0; d < DD; d++) {
        float b = g_tnT[d*BB + j];
        #pragma unroll
        for (int rr = 0; rr < 16; rr++) acc[rr] += sV[d*17 + rr] * b;
    }

    int labj = labels[j];
    float lsum = 0.f;
    #pragma unroll
    for (int rr = 0; rr < 16; rr++) {
        bool match = (labels[rg*16 + rr] == labj);
        float s = acc[rr];
        lsum += match ? softplus_f(-SP_ * (s - ALPHA_)) : softplus_f(SN_ * (s - BETA_));
    }
    blockAtomicAddF(lsum, &g_accGlob, swarp);
}

__device__ void do_boost(char* smraw, int p) {
    float* srow = (float*)smraw;
    float* scol = (float*)(smraw + 1024);
    int c = threadIdx.x;
    const float* S = g_sims + (size_t)p*BB*BB;
    srow[c] = S[(size_t)p*BB + c];
    scol[c] = S[(size_t)c*BB + p];
    __syncthreads();

    float vr = srow[c];
    int cnt = 0;
    for (int k = 0; k < BB; k++) { float o = srow[k]; cnt += (o > vr) || (o == vr && k < c); }
    bool inRow = cnt < 8;
    cnt = 0;
    for (int r = 0; r < BB; r++) { float o = S[(size_t)r*BB + c]; cnt += (o > vr) || (o == vr && r < p); }
    bool inCol = cnt < 8;
    g_boost1[p*BB + c] = (inRow && inCol) ? 1 : 0;

    float vc = scol[c];
    cnt = 0;
    for (int k = 0; k < BB; k++) { float o = scol[k]; cnt += (o > vc) || (o == vc && k < c); }
    bool inColP = cnt < 8;
    cnt = 0;
    for (int cc = 0; cc < BB; cc++) { float o = S[(size_t)c*BB + cc]; cnt += (o > vc) || (o == vc && cc < p); }
    bool inRowR = cnt < 8;
    g_boost2[p*BB + c] = (inColP && inRowR) ? 1 : 0;
    __syncthreads();
}

__device__ void do_reduce(int task) {
    int w = threadIdx.x >> 5, lane = threadIdx.x & 31;
    int row = task * 8 + w;
    float m = -INFINITY;
    for (int j = lane; j < NCHUNK; j += 32) m = fmaxf(m, g_chunkMax[j*512 + row]);
    #pragma unroll
    for (int off = 16; off > 0; off >>= 1) m = fmaxf(m, __shfl_xor_sync(0xffffffffu, m, off));
    float s = 0.f;
    for (int j = lane; j < NCHUNK; j += 32) s += g_chunkSum[j*512 + row] * fexp(g_chunkMax[j*512 + row] - m);
    s = warpReduceF(s);
    if (lane == 0) g_rowLoss[row] = m + flog(s) - g_labLogit[row];
}

__device__ void do_local(int task, const int* __restrict__ labels,
                         const uint8_t* __restrict__ vmask, const uint8_t* __restrict__ tmask) {
    __shared__ float swarp[8];
    int r = task & 255;
    int p = task >> 8;
    int c = threadIdx.x;

    int vmInt = g_vmInt, tmInt = g_tmInt;
    float s = g_sims[((size_t)p*BB + r)*BB + c];
    bool match = (labels[r] == labels[c]);
    float Lp = softplus_f(-SP_ * (s - ALPHA_));
    float Ln = softplus_f(SN_ * (s - BETA_));

    bool pmr = readMask(vmask, r*PP + p, vmInt);
    bool pmc = readMask(vmask, c*PP + p, vmInt);
    bool amc = readMask(tmask, c*PP + p, tmInt);

    float val = 0.f;
    if (pmr && amc) val += (match || g_boost1[p*BB + c]) ? Lp : Ln;
    if (pmr && pmc && amc) val += (match || g_boost2[p*BB + r]) ? Lp : Ln;

    blockAtomicAddF(val, &g_accLocal, swarp);
}

__device__ void do_finalize(char* smraw, float* __restrict__ out) {
    double* sred = (double*)smraw;
    int t = threadIdx.x;
    sred[t] = (double)g_rowLoss[t] + (double)g_rowLoss[t + 256];
    __syncthreads();
    for (int s = 128; s > 0; s >>= 1) {
        if (t < s) sred[t] += sred[t + s];
        __syncthreads();
    }
    if (t == 0) {
        out[0] = (float)(sred[0] / 256.0);
        out[1] = (float)(5.0 * g_accMask / ((double)NPIX));
        out[2] = (float)(2.0 * g_accGlob / 256.0);
        out[3] = (float)(g_accLocal / (256.0 * 5.0));
    }
    __syncthreads();
}

// ================= mega kernel =================
__global__ __launch_bounds__(256, 2) void mega_kernel(
    const float* __restrict__ visual, const float* __restrict__ textual,
    const float* __restrict__ part, const float* __restrict__ attribute,
    const float* __restrict__ seg, const float* __restrict__ W,
    const int* __restrict__ labels, const int* __restrict__ masks,
    const uint8_t* __restrict__ vmask, const uint8_t* __restrict__ tmask,
    float* __restrict__ out)
{
    extern __shared__ __align__(16) char sm[];
    __shared__ int s_task;
    const int NBLK = gridDim.x;

    // ---- Phase 0: cvtW + normalize + detect (GEMM prerequisites only) ----
    {
        const int T_CVTW = 344 * 16;                 // 5504
        const int T_NORM = 512 + 2*PP*BB;            // 3072
        const int TOT = T_CVTW + T_NORM + 1;
        for (;;) {
            __syncthreads();
            if (threadIdx.x == 0) s_task = atomicAdd(&g_work[0], 1);
            __syncthreads();
            int task = s_task;
            if (task >= TOT) break;
            if (task < T_CVTW) do_cvtW(sm, task, W);
            else if (task < T_CVTW + T_NORM) do_normalize(sm, task - T_CVTW, visual, textual, part, attribute);
            else do_detect(vmask, tmask);
        }
    }
    gridBarrier(0, NBLK);

    // ---- Phase 1: GEMM tiles (first) + mask (DRAM-bound, overlaps) + sims + global ----
    {
        const int T_GEMM = NCHUNK * 4;               // 688
        const int T_MASK = NPIX / 2048;              // 2560 (8 px/thread)
        const int TOT = T_GEMM + T_MASK + 80 + 16;
        for (;;) {
            __syncthreads();
            if (threadIdx.x == 0) s_task = atomicAdd(&g_work[1], 1);
            __syncthreads();
            int task = s_task;
            if (task >= TOT) break;
            if (task < T_GEMM) do_gemm(sm, task % NCHUNK, task / NCHUNK, labels);
            else if (task < T_GEMM + T_MASK) do_mask(task - T_GEMM, seg, masks);
            else if (task < T_GEMM + T_MASK + 80) { int u = task - T_GEMM - T_MASK; do_sims(sm, u & 15, u >> 4); }
            else do_global(sm, task - T_GEMM - T_MASK - 80, labels);
        }
    }
    gridBarrier(1, NBLK);

    // ---- Phase 2: boost + instance reduce ----
    {
        const int TOT = 5 + 64;
        for (;;) {
            __syncthreads();
            if (threadIdx.x == 0) s_task = atomicAdd(&g_work[2], 1);
            __syncthreads();
            int task = s_task;
            if (task >= TOT) break;
            if (task < 5) do_boost(sm, task);
            else do_reduce(task - 5);
        }
    }
    gridBarrier(2, NBLK);

    // ---- Phase 3: local align ----
    {
        const int TOT = BB * PP;                     // 1280
        for (;;) {
            __syncthreads();
            if (threadIdx.x == 0) s_task = atomicAdd(&g_work[3], 1);
            __syncthreads();
            int task = s_task;
            if (task >= TOT) break;
            do_local(task, labels, vmask, tmask);
        }
    }
    gridBarrier(3, NBLK);

    // ---- finalize + state reset (block 0 only) ----
    if (blockIdx.x == 0) {
        do_finalize(sm, out);
        if (threadIdx.x == 0) {
            for (int ph = 0; ph < 4; ph++)
                while (*(volatile int*)&g_dep[ph] < NBLK) __nanosleep(64);
            for (int ph = 0; ph < 4; ph++) { g_arr[ph] = 0; g_dep[ph] = 0; g_work[ph] = 0; }
            g_accMask = 0.0; g_accGlob = 0.0; g_accLocal = 0.0;
            __threadfence();
        }
        __syncthreads();
        for (int i = threadIdx.x; i < NCPAD; i += 256) g_sumsq[i] = 0.f;
    }
}

// ---------------- launch ----------------
extern "C" void kernel_launch(void* const* d_in, const int* in_sizes, int n_in,
                              void* d_out, int out_size) {
    const float* visual    = (const float*)d_in[0];
    const float* textual   = (const float*)d_in[1];
    const float* part      = (const float*)d_in[2];
    const float* attribute = (const float*)d_in[3];
    const float* seg       = (const float*)d_in[4];
    const float* W         = (const float*)d_in[5];
    const int*   labels    = (const int*)d_in[6];
    const int*   masks     = (const int*)d_in[7];
    const uint8_t* vmask   = (const uint8_t*)d_in[8];
    const uint8_t* tmask   = (const uint8_t*)d_in[9];
    float* out = (float*)d_out;

    static int grid = 0;
    if (!grid) {
        cudaFuncSetAttribute(mega_kernel, cudaFuncAttributeMaxDynamicSharedMemorySize, GEMM_SMEM);
        int nsm = 0, occ = 0;
        cudaDeviceGetAttribute(&nsm, cudaDevAttrMultiProcessorCount, 0);
        cudaOccupancyMaxActiveBlocksPerMultiprocessor(&occ, mega_kernel, 256, GEMM_SMEM);
        if (nsm <= 0) nsm = 148;
        if (occ < 1) occ = 1;
        if (occ > 2) occ = 2;
        grid = nsm * occ;
    }

    mega_kernel<<<grid, 256, GEMM_SMEM>>>(visual, textual, part, attribute, seg, W,
                                          labels, masks, vmask, tmask, out);
}

// round 12
// speedup vs baseline: 1.1581x; 1.0835x over previous
#include <cuda_runtime.h>
#include <cuda_bf16.h>
#include <math.h>
#include <stdint.h>

#define BB 256
#define DD 512
#define PP 5
#define NC 11003
#define NCPAD 11008
#define SEGC 6
#define SCALE_ 28.0f
#define ALPHA_ 0.6f
#define BETA_ 0.4f
#define SP_ 10.0f
#define SN_ 40.0f

#define NCHUNK 172         // ceil(11008/64)
#define NPIX (1280*4096)

// ---------------- device scratch ----------------
__device__ float g_XN[2*BB*DD];
__device__ float g_tnT[DD*BB];
__device__ float g_penN[PP*BB*DD];
__device__ float g_aeT[PP*DD*BB];
__device__ float g_sumsq[NCPAD];               // zeroed at end of each run (and at load)
__device__ __align__(16) __nv_bfloat16 g_Ahi[2*BB*DD];
__device__ __align__(16) __nv_bfloat16 g_Alo[2*BB*DD];
__device__ __align__(16) __nv_bfloat16 g_Bhi[NCPAD*DD];
__device__ __align__(16) __nv_bfloat16 g_Blo[NCPAD*DD];
__device__ float g_chunkMax[NCHUNK*2*BB];
__device__ float g_chunkSum[NCHUNK*2*BB];
__device__ float g_labLogit[2*BB];
__device__ float g_rowLoss[2*BB];
__device__ float g_sims[PP*BB*BB];
__device__ int   g_boost1[PP*BB];
__device__ int   g_boost2[PP*BB];
__device__ int   g_vmInt, g_tmInt;
__device__ double g_accMask, g_accGlob, g_accLocal;
__device__ int g_work[4];
__device__ int g_arr[4], g_dep[4];

// ---------------- fast transcendentals (FMA-only) ----------------
__device__ __forceinline__ float fexp(float x) {
    x = fmaxf(fminf(x, 88.0f), -87.0f);
    float t = x * 1.4426950408889634f;
    float z = t + 12582912.0f;
    int i = __float_as_int(z) - 0x4B400000;
    float f = t - (z - 12582912.0f);
    float p = 1.5252733804059841e-05f;
    p = fmaf(p, f, 1.5403530393381610e-04f);
    p = fmaf(p, f, 1.3333558146428443e-03f);
    p = fmaf(p, f, 9.6181291076284772e-03f);
    p = fmaf(p, f, 5.5504108664821580e-02f);
    p = fmaf(p, f, 2.4022650695910071e-01f);
    p = fmaf(p, f, 6.9314718055994531e-01f);
    p = fmaf(p, f, 1.0f);
    return __int_as_float((i + 127) << 23) * p;
}
__device__ __forceinline__ float flog(float x) {
    int ix = __float_as_int(x);
    int e = (ix - 0x3f3504f3) >> 23;
    float m = __int_as_float(ix - (e << 23));
    float u = m - 1.0f;
    float z = u * u;
    float p = 7.0376836292e-2f;
    p = fmaf(p, u, -1.1514610310e-1f);
    p = fmaf(p, u,  1.1676998740e-1f);
    p = fmaf(p, u, -1.2420140846e-1f);
    p = fmaf(p, u,  1.4249322787e-1f);
    p = fmaf(p, u, -1.6668057665e-1f);
    p = fmaf(p, u,  2.0000714765e-1f);
    p = fmaf(p, u, -2.4999993993e-1f);
    p = fmaf(p, u,  3.3333331174e-1f);
    float y = p * u * z - 0.5f * z;
    return fmaf((float)e, 0.69314718055994531f, u + y);
}
__device__ __forceinline__ float softplus_f(float x) {
    if (x > 20.f) return x;
    return flog(1.0f + fexp(x));
}
__device__ __forceinline__ float warpReduceF(float v) {
    #pragma unroll
    for (int off = 16; off > 0; off >>= 1) v += __shfl_xor_sync(0xffffffffu, v, off);
    return v;
}
__device__ __forceinline__ void blockAtomicAddF(float v, double* target, float* swarp) {
    int w = threadIdx.x >> 5, lane = threadIdx.x & 31;
    v = warpReduceF(v);
    if (lane == 0) swarp[w] = v;
    __syncthreads();
    if (threadIdx.x == 0) {
        float s = 0.f;
        for (int i = 0; i < 8; i++) s += swarp[i];
        atomicAdd(target, (double)s);
    }
    __syncthreads();
}
__device__ __forceinline__ bool readMask(const uint8_t* m, int idx, int isInt) {
    return isInt ? (((const int*)m)[idx] != 0) : (m[idx] != 0);
}
__device__ __forceinline__ float rsqrt_nt(float s) {
    float inv = rsqrtf(s);
    return inv * (1.5f - 0.5f * s * inv * inv);
}
__device__ __forceinline__ void mma_bf16(float* c, const uint32_t* a, const uint32_t* b) {
    asm volatile(
        "mma.sync.aligned.m16n8k16.row.col.f32.bf16.bf16.f32 "
        "{%0,%1,%2,%3}, {%4,%5,%6,%7}, {%8,%9}, {%0,%1,%2,%3};"
        : "+f"(c[0]), "+f"(c[1]), "+f"(c[2]), "+f"(c[3])
        : "r"(a[0]), "r"(a[1]), "r"(a[2]), "r"(a[3]), "r"(b[0]), "r"(b[1]));
}
__device__ __forceinline__ void ldsm_x4(uint32_t& r0, uint32_t& r1, uint32_t& r2, uint32_t& r3, uint32_t addr) {
    asm volatile("ldmatrix.sync.aligned.m8n8.x4.shared.b16 {%0,%1,%2,%3}, [%4];"
                 : "=r"(r0), "=r"(r1), "=r"(r2), "=r"(r3) : "r"(addr));
}

// ---------------- grid barrier (arrive/depart, replay-safe) ----------------
__device__ __forceinline__ void gridBarrier(int ph, int nb) {
    __syncthreads();
    if (threadIdx.x == 0) {
        __threadfence();
        atomicAdd(&g_arr[ph], 1);
        while (*(volatile int*)&g_arr[ph] < nb) __nanosleep(64);
        __threadfence();
        atomicAdd(&g_dep[ph], 1);
    }
    __syncthreads();
}

// ================= phase bodies =================

// mask loss: 8 pixels per thread
__device__ void do_mask(int mblk, const float* __restrict__ seg, const int* __restrict__ masks) {
    __shared__ float swarp[8];
    int tid = mblk * 256 + threadIdx.x;
    long long pix0 = (long long)tid * 8;
    int n = (int)(pix0 >> 12);
    int hw = (int)(pix0 & 4095);
    const float* base = seg + (size_t)n * SEGC * 4096 + hw;

    float xx[SEGC][8];
    #pragma unroll
    for (int c = 0; c < SEGC; c++) {
        float4 v0 = *(const float4*)(base + (size_t)c * 4096);
        float4 v1 = *(const float4*)(base + (size_t)c * 4096 + 4);
        xx[c][0] = v0.x; xx[c][1] = v0.y; xx[c][2] = v0.z; xx[c][3] = v0.w;
        xx[c][4] = v1.x; xx[c][5] = v1.y; xx[c][6] = v1.z; xx[c][7] = v1.w;
    }
    int4 ca = *(const int4*)(masks + pix0);
    int4 cb = *(const int4*)(masks + pix0 + 4);
    int cls[8] = {ca.x, ca.y, ca.z, ca.w, cb.x, cb.y, cb.z, cb.w};

    float acc = 0.f;
    #pragma unroll
    for (int j = 0; j < 8; j++) {
        float m = xx[0][j];
        #pragma unroll
        for (int c = 1; c < SEGC; c++) m = fmaxf(m, xx[c][j]);
        float s = 0.f, sel = 0.f;
        #pragma unroll
        for (int c = 0; c < SEGC; c++) {
            s += fexp(xx[c][j] - m);
            sel += (c == cls[j]) ? xx[c][j] : 0.f;
        }
        acc += m + flog(s) - sel;
    }
    blockAtomicAddF(acc, &g_accMask, swarp);
}

__device__ void do_cvtW(char* smraw, int task, const float* __restrict__ W) {
    float (*tile)[33] = (float(*)[33])smraw;
    int tx = threadIdx.x & 31, ty = threadIdx.x >> 5;
    int c0 = (task % 344) * 32, d0 = (task / 344) * 32;
    #pragma unroll
    for (int i = 0; i < 4; i++) {
        int d = d0 + ty + i*8, c = c0 + tx;
        tile[ty + i*8][tx] = (c < NC) ? W[(size_t)d*NC + c] : 0.f;
    }
    __syncthreads();
    #pragma unroll
    for (int i = 0; i < 4; i++) {
        int cl = ty + i*8;
        int c = c0 + cl, d = d0 + tx;
        float v = tile[tx][cl];
        __nv_bfloat16 hi = __float2bfloat16(v);
        g_Bhi[(size_t)c*DD + d] = hi;
        g_Blo[(size_t)c*DD + d] = __float2bfloat16(v - __bfloat162float(hi));
        float ss = warpReduceF(v * v);
        if (tx == 0) atomicAdd(&g_sumsq[c], ss);
    }
    __syncthreads();
}

__device__ void do_normalize(char* smraw, int b, const float* __restrict__ v, const float* __restrict__ t,
                             const float* __restrict__ pe, const float* __restrict__ ae) {
    float* sred = (float*)smraw;
    const float* src;
    float* dst = nullptr;
    float* dstT = nullptr;
    int tcol = 0;
    bool isXN = false;
    if (b < 256) { src = v + (size_t)b*DD; dst = g_XN + (size_t)b*DD; isXN = true; }
    else if (b < 512) { int r = b - 256; src = t + (size_t)r*DD; dst = g_XN + (size_t)b*DD; dstT = g_tnT; tcol = r; isXN = true; }
    else if (b < 512 + PP*BB) { int k = b - 512; src = pe + (size_t)k*DD; dst = g_penN + (size_t)k*DD; }
    else { int k = b - 512 - PP*BB; int p = k / BB; int rr = k % BB;
           src = ae + (size_t)k*DD; dstT = g_aeT + (size_t)p*DD*BB; tcol = rr; }

    float s = 0.f;
    for (int d = threadIdx.x; d < DD; d += 256) { float x = src[d]; s += x*x; }
    sred[threadIdx.x] = s; __syncthreads();
    for (int st = 128; st > 0; st >>= 1) { if (threadIdx.x < st) sred[threadIdx.x] += sred[threadIdx.x + st]; __syncthreads(); }
    float inv = rsqrt_nt(sred[0]);
    __syncthreads();

    for (int d = threadIdx.x; d < DD; d += 256) {
        float x = src[d] * inv;
        if (dst)  dst[d] = x;
        if (dstT) dstT[d*BB + tcol] = x;
        if (isXN) {
            __nv_bfloat16 hi = __float2bfloat16(x);
            g_Ahi[(size_t)b*DD + d] = hi;
            g_Alo[(size_t)b*DD + d] = __float2bfloat16(x - __bfloat162float(hi));
        }
    }
}

__device__ void do_detect(const uint8_t* __restrict__ vm, const uint8_t* __restrict__ tm) {
    __shared__ int s0, s1;
    if (threadIdx.x == 0) { s0 = 0; s1 = 0; }
    __syncthreads();
    int a0 = 0, a1 = 0;
    for (int i = threadIdx.x; i < PP*BB; i += 256) {
        if (i & 3) { a0 |= vm[i]; a1 |= tm[i]; }
    }
    atomicOr(&s0, a0); atomicOr(&s1, a1);
    __syncthreads();
    if (threadIdx.x == 0) { g_vmInt = (s0 == 0) ? 1 : 0; g_tmInt = (s1 == 0) ? 1 : 0; }
}

// ---- GEMM tile (128 rows x 64 cols, K=512) — R8 body, unchanged ----
#define SA_STRIDE 72
#define OFF_AH 0
#define OFF_AL 18432
#define OFF_BH 36864
#define OFF_BL 46080
#define GEMM_SMEM 55296

__device__ void do_gemm(char* smraw, int chunk, int rt, const int* __restrict__ labels) {
    __nv_bfloat16* sAh = (__nv_bfloat16*)(smraw + OFF_AH);
    __nv_bfloat16* sAl = (__nv_bfloat16*)(smraw + OFF_AL);
    __nv_bfloat16* sBh = (__nv_bfloat16*)(smraw + OFF_BH);
    __nv_bfloat16* sBl = (__nv_bfloat16*)(smraw + OFF_BL);
    __shared__ float sInv[64];

    const int rowBase = rt * 128;
    const int colBase = chunk * 64;
    const int t = threadIdx.x;
    const int w = t >> 5, lane = t & 31;
    const int lr = lane & 7, mi = lane >> 3;
    const uint32_t sbase = (uint32_t)__cvta_generic_to_shared(smraw);

    const uint32_t aoff = (uint32_t)((w*16 + lr + (mi & 1)*8) * SA_STRIDE + (mi >> 1)*8) * 2;
    uint32_t boff[4];
    #pragma unroll
    for (int q = 0; q < 4; q++)
        boff[q] = (uint32_t)((q*16 + (mi >> 1)*8 + lr) * SA_STRIDE + (mi & 1)*8) * 2;

    float acc[8][4];
    #pragma unroll
    for (int nf = 0; nf < 8; nf++)
        #pragma unroll
        for (int q = 0; q < 4; q++) acc[nf][q] = 0.f;

    const __nv_bfloat16* Ahi = g_Ahi + (size_t)rowBase*DD;
    const __nv_bfloat16* Alo = g_Alo + (size_t)rowBase*DD;
    const __nv_bfloat16* Bhi = g_Bhi + (size_t)colBase*DD;
    const __nv_bfloat16* Blo = g_Blo + (size_t)colBase*DD;

    if (t < 64) sInv[t] = rsqrt_nt(g_sumsq[colBase + t]);

    for (int kc = 0; kc < 8; kc++) {
        int k0g = kc * 64;
        #pragma unroll
        for (int it = 0; it < 4; it++) {
            int idx = t + it*256, row = idx >> 3, j = idx & 7;
            ((uint4*)sAh)[row*9 + j] = ((const uint4*)(Ahi + (size_t)row*DD + k0g))[j];
            ((uint4*)sAl)[row*9 + j] = ((const uint4*)(Alo + (size_t)row*DD + k0g))[j];
        }
        #pragma unroll
        for (int it = 0; it < 2; it++) {
            int idx = t + it*256, row = idx >> 3, j = idx & 7;
            ((uint4*)sBh)[row*9 + j] = ((const uint4*)(Bhi + (size_t)row*DD + k0g))[j];
            ((uint4*)sBl)[row*9 + j] = ((const uint4*)(Blo + (size_t)row*DD + k0g))[j];
        }
        __syncthreads();

        #pragma unroll
        for (int ks = 0; ks < 4; ks++) {
            uint32_t kadd = ks * 32;
            uint32_t ah[4], al[4];
            ldsm_x4(ah[0], ah[1], ah[2], ah[3], sbase + OFF_AH + aoff + kadd);
            ldsm_x4(al[0], al[1], al[2], al[3], sbase + OFF_AL + aoff + kadd);
            #pragma unroll
            for (int q = 0; q < 4; q++) {
                uint32_t bh[4], bl[4];
                ldsm_x4(bh[0], bh[1], bh[2], bh[3], sbase + OFF_BH + boff[q] + kadd);
                ldsm_x4(bl[0], bl[1], bl[2], bl[3], sbase + OFF_BL + boff[q] + kadd);
                mma_bf16(acc[2*q],   ah, bh);
                mma_bf16(acc[2*q],   al, bh);
                mma_bf16(acc[2*q],   ah, bl);
                mma_bf16(acc[2*q+1], ah, bh+2);
                mma_bf16(acc[2*q+1], al, bh+2);
                mma_bf16(acc[2*q+1], ah, bl+2);
            }
        }
        __syncthreads();
    }

    const int g = lane >> 2, tig = lane & 3;
    #pragma unroll
    for (int h = 0; h < 2; h++) {
        int gr = rowBase + w*16 + g + h*8;
        int lab = labels[gr & 255];
        float lg[8][2];
        float m = -INFINITY;
        #pragma unroll
        for (int nf = 0; nf < 8; nf++) {
            #pragma unroll
            for (int j = 0; j < 2; j++) {
                int lc = nf*8 + tig*2 + j;
                int col = colBase + lc;
                float x;
                if (col < NC) {
                    x = SCALE_ * acc[nf][h*2 + j] * sInv[lc];
                    if (col == lab) g_labLogit[gr] = x;
                } else {
                    x = -INFINITY;
                }
                lg[nf][j] = x;
                m = fmaxf(m, x);
            }
        }
        m = fmaxf(m, __shfl_xor_sync(0xffffffffu, m, 1));
        m = fmaxf(m, __shfl_xor_sync(0xffffffffu, m, 2));
        float s = 0.f;
        #pragma unroll
        for (int nf = 0; nf < 8; nf++)
            #pragma unroll
            for (int j = 0; j < 2; j++) s += fexp(lg[nf][j] - m);
        s += __shfl_xor_sync(0xffffffffu, s, 1);
        s += __shfl_xor_sync(0xffffffffu, s, 2);
        if (tig == 0) {
            g_chunkMax[chunk*512 + gr] = m;
            g_chunkSum[chunk*512 + gr] = s;
        }
    }
}

__device__ void do_sims(char* smraw, int rg, int p) {
    float* sP = (float*)smraw;
    int j = threadIdx.x;
    for (int idx = j; idx < 16*DD; idx += 256) {
        int rr = idx / DD, d = idx % DD;
        sP[d*17 + rr] = g_penN[((size_t)p*BB + rg*16 + rr)*DD + d];
    }
    __syncthreads();

    float acc[16];
    #pragma unroll
    for (int rr = 0; rr < 16; rr++) acc[rr] = 0.f;
    const float* aT = g_aeT + (size_t)p*DD*BB;
    for (int d = 0; d < DD; d++) {
        float b = aT[d*BB + j];
        #pragma unroll
        for (int rr = 0; rr < 16; rr++) acc[rr] += sP[d*17 + rr] * b;
    }
    float* S = g_sims + (size_t)p*BB*BB;
    #pragma unroll
    for (int rr = 0; rr < 16; rr++) S[(size_t)(rg*16 + rr)*BB + j] = acc[rr];
    __syncthreads();
}

__device__ void do_global(char* smraw, int rg, const int* __restrict__ labels) {
    float* sV = (float*)smraw;
    __shared__ float swarp[8];
    int j = threadIdx.x;
    for (int idx = j; idx < 16*DD; idx += 256) {
        int rr = idx / DD, d = idx % DD;
        sV[d*17 + rr] = g_XN[(size_t)(rg*16 + rr)*DD + d];
    }
    __syncthreads();

    float acc[16];
    #pragma unroll
    for (int rr = 0; rr < 16; rr++) acc[rr] = 0.f;
    for (int d = 0; d < DD; d++) {
        float b = g_tnT[d*BB + j];
        #pragma unroll
        for (int rr = 0; rr < 16; rr++) acc[rr] += sV[d*17 + rr] * b;
    }

    int labj = labels[j];
    float lsum = 0.f;
    #pragma unroll
    for (int rr = 0; rr < 16; rr++) {
        bool match = (labels[rg*16 + rr] == labj);
        float s = acc[rr];
        lsum += match ? softplus_f(-SP_ * (s - ALPHA_)) : softplus_f(SN_ * (s - BETA_));
    }
    blockAtomicAddF(lsum, &g_accGlob, swarp);
}

__device__ void do_boost(char* smraw, int p) {
    float* srow = (float*)smraw;
    float* scol = (float*)(smraw + 1024);
    int c = threadIdx.x;
    const float* S = g_sims + (size_t)p*BB*BB;
    srow[c] = S[(size_t)p*BB + c];
    scol[c] = S[(size_t)c*BB + p];
    __syncthreads();

    float vr = srow[c];
    int cnt = 0;
    for (int k = 0; k < BB; k++) { float o = srow[k]; cnt += (o > vr) || (o == vr && k < c); }
    bool inRow = cnt < 8;
    cnt = 0;
    for (int r = 0; r < BB; r++) { float o = S[(size_t)r*BB + c]; cnt += (o > vr) || (o == vr && r < p); }
    bool inCol = cnt < 8;
    g_boost1[p*BB + c] = (inRow && inCol) ? 1 : 0;

    float vc = scol[c];
    cnt = 0;
    for (int k = 0; k < BB; k++) { float o = scol[k]; cnt += (o > vc) || (o == vc && k < c); }
    bool inColP = cnt < 8;
    cnt = 0;
    for (int cc = 0; cc < BB; cc++) { float o = S[(size_t)c*BB + cc]; cnt += (o > vc) || (o == vc && cc < p); }
    bool inRowR = cnt < 8;
    g_boost2[p*BB + c] = (inColP && inRowR) ? 1 : 0;
    __syncthreads();
}

__device__ void do_reduce(int task) {
    int w = threadIdx.x >> 5, lane = threadIdx.x & 31;
    int row = task * 8 + w;
    float m = -INFINITY;
    for (int j = lane; j < NCHUNK; j += 32) m = fmaxf(m, g_chunkMax[j*512 + row]);
    #pragma unroll
    for (int off = 16; off > 0; off >>= 1) m = fmaxf(m, __shfl_xor_sync(0xffffffffu, m, off));
    float s = 0.f;
    for (int j = lane; j < NCHUNK; j += 32) s += g_chunkSum[j*512 + row] * fexp(g_chunkMax[j*512 + row] - m);
    s = warpReduceF(s);
    if (lane == 0) g_rowLoss[row] = m + flog(s) - g_labLogit[row];
}

__device__ void do_local(int task, const int* __restrict__ labels,
                         const uint8_t* __restrict__ vmask, const uint8_t* __restrict__ tmask) {
    __shared__ float swarp[8];
    int r = task & 255;
    int p = task >> 8;
    int c = threadIdx.x;

    int vmInt = g_vmInt, tmInt = g_tmInt;
    float s = g_sims[((size_t)p*BB + r)*BB + c];
    bool match = (labels[r] == labels[c]);
    float Lp = softplus_f(-SP_ * (s - ALPHA_));
    float Ln = softplus_f(SN_ * (s - BETA_));

    bool pmr = readMask(vmask, r*PP + p, vmInt);
    bool pmc = readMask(vmask, c*PP + p, vmInt);
    bool amc = readMask(tmask, c*PP + p, tmInt);

    float val = 0.f;
    if (pmr && amc) val += (match || g_boost1[p*BB + c]) ? Lp : Ln;
    if (pmr && pmc && amc) val += (match || g_boost2[p*BB + r]) ? Lp : Ln;

    blockAtomicAddF(val, &g_accLocal, swarp);
}

__device__ void do_finalize(char* smraw, float* __restrict__ out) {
    double* sred = (double*)smraw;
    int t = threadIdx.x;
    sred[t] = (double)g_rowLoss[t] + (double)g_rowLoss[t + 256];
    __syncthreads();
    for (int s = 128; s > 0; s >>= 1) {
        if (t < s) sred[t] += sred[t + s];
        __syncthreads();
    }
    if (t == 0) {
        out[0] = (float)(sred[0] / 256.0);
        out[1] = (float)(5.0 * g_accMask / ((double)NPIX));
        out[2] = (float)(2.0 * g_accGlob / 256.0);
        out[3] = (float)(g_accLocal / (256.0 * 5.0));
    }
    __syncthreads();
}

// ================= mega kernel =================
__global__ __launch_bounds__(256, 3) void mega_kernel(
    const float* __restrict__ visual, const float* __restrict__ textual,
    const float* __restrict__ part, const float* __restrict__ attribute,
    const float* __restrict__ seg, const float* __restrict__ W,
    const int* __restrict__ labels, const int* __restrict__ masks,
    const uint8_t* __restrict__ vmask, const uint8_t* __restrict__ tmask,
    float* __restrict__ out)
{
    extern __shared__ __align__(16) char sm[];
    __shared__ int s_task;
    const int NBLK = gridDim.x;

    // ---- Phase 0: cvtW + normalize + detect (GEMM prerequisites only) ----
    {
        const int T_CVTW = 344 * 16;                 // 5504
        const int T_NORM = 512 + 2*PP*BB;            // 3072
        const int TOT = T_CVTW + T_NORM + 1;
        for (;;) {
            __syncthreads();
            if (threadIdx.x == 0) s_task = atomicAdd(&g_work[0], 1);
            __syncthreads();
            int task = s_task;
            if (task >= TOT) break;
            if (task < T_CVTW) do_cvtW(sm, task, W);
            else if (task < T_CVTW + T_NORM) do_normalize(sm, task - T_CVTW, visual, textual, part, attribute);
            else do_detect(vmask, tmask);
        }
    }
    gridBarrier(0, NBLK);

    // ---- Phase 1: GEMM tiles (rt-fastest: 4 row-tiles of a chunk run together,
    //       keeping the B chunk L2-hot) + mask + sims + global ----
    {
        const int T_GEMM = NCHUNK * 4;               // 688
        const int T_MASK = NPIX / 2048;              // 2560 (8 px/thread)
        const int TOT = T_GEMM + T_MASK + 80 + 16;
        for (;;) {
            __syncthreads();
            if (threadIdx.x == 0) s_task = atomicAdd(&g_work[1], 1);
            __syncthreads();
            int task = s_task;
            if (task >= TOT) break;
            if (task < T_GEMM) do_gemm(sm, task >> 2, task & 3, labels);
            else if (task < T_GEMM + T_MASK) do_mask(task - T_GEMM, seg, masks);
            else if (task < T_GEMM + T_MASK + 80) { int u = task - T_GEMM - T_MASK; do_sims(sm, u & 15, u >> 4); }
            else do_global(sm, task - T_GEMM - T_MASK - 80, labels);
        }
    }
    gridBarrier(1, NBLK);

    // ---- Phase 2: boost + instance reduce ----
    {
        const int TOT = 5 + 64;
        for (;;) {
            __syncthreads();
            if (threadIdx.x == 0) s_task = atomicAdd(&g_work[2], 1);
            __syncthreads();
            int task = s_task;
            if (task >= TOT) break;
            if (task < 5) do_boost(sm, task);
            else do_reduce(task - 5);
        }
    }
    gridBarrier(2, NBLK);

    // ---- Phase 3: local align ----
    {
        const int TOT = BB * PP;                     // 1280
        for (;;) {
            __syncthreads();
            if (threadIdx.x == 0) s_task = atomicAdd(&g_work[3], 1);
            __syncthreads();
            int task = s_task;
            if (task >= TOT) break;
            do_local(task, labels, vmask, tmask);
        }
    }
    gridBarrier(3, NBLK);

    // ---- finalize + state reset (block 0 only) ----
    if (blockIdx.x == 0) {
        do_finalize(sm, out);
        if (threadIdx.x == 0) {
            for (int ph = 0; ph < 4; ph++)
                while (*(volatile int*)&g_dep[ph] < NBLK) __nanosleep(64);
            for (int ph = 0; ph < 4; ph++) { g_arr[ph] = 0; g_dep[ph] = 0; g_work[ph] = 0; }
            g_accMask = 0.0; g_accGlob = 0.0; g_accLocal = 0.0;
            __threadfence();
        }
        __syncthreads();
        for (int i = threadIdx.x; i < NCPAD; i += 256) g_sumsq[i] = 0.f;
    }
}

// ---------------- launch ----------------
extern "C" void kernel_launch(void* const* d_in, const int* in_sizes, int n_in,
                              void* d_out, int out_size) {
    const float* visual    = (const float*)d_in[0];
    const float* textual   = (const float*)d_in[1];
    const float* part      = (const float*)d_in[2];
    const float* attribute = (const float*)d_in[3];
    const float* seg       = (const float*)d_in[4];
    const float* W         = (const float*)d_in[5];
    const int*   labels    = (const int*)d_in[6];
    const int*   masks     = (const int*)d_in[7];
    const uint8_t* vmask   = (const uint8_t*)d_in[8];
    const uint8_t* tmask   = (const uint8_t*)d_in[9];
    float* out = (float*)d_out;

    static int grid = 0;
    if (!grid) {
        cudaFuncSetAttribute(mega_kernel, cudaFuncAttributeMaxDynamicSharedMemorySize, GEMM_SMEM);
        int nsm = 0, occ = 0;
        cudaDeviceGetAttribute(&nsm, cudaDevAttrMultiProcessorCount, 0);
        cudaOccupancyMaxActiveBlocksPerMultiprocessor(&occ, mega_kernel, 256, GEMM_SMEM);
        if (nsm <= 0) nsm = 148;
        if (occ < 1) occ = 1;
        if (occ > 3) occ = 3;
        grid = nsm * occ;
    }

    mega_kernel<<<grid, 256, GEMM_SMEM>>>(visual, textual, part, attribute, seg, W,
                                          labels, masks, vmask, tmask, out);
}